// round 2
// baseline (speedup 1.0000x reference)
#include <cuda_runtime.h>
#include <math.h>

// ---------------------------------------------------------------------------
// Shapes (reference: N=50000, IN=500, H1=512, H2=256)
// ---------------------------------------------------------------------------
#define MAXN  50048
#define MAXH1 512
#define MAXH2 256

// Scratch: three N x H1 buffers with lifetime aliasing (layer-2 sub-buffers
// live inside them). ~308 MB total static device memory.
__device__ float g_bufA[MAXN * MAXH1];
__device__ float g_bufB[MAXN * MAXH1];
__device__ float g_bufC[MAXN * MAXH1];
__device__ float g_dinv[MAXN];
__device__ float g_colsum[MAXH1];
__device__ float g_colsq [MAXH1];
__device__ float g_scale [MAXH1];
__device__ float g_shift [MAXH1];
__device__ float g_pnsum [MAXH1];
__device__ float g_pnmean[MAXH1];
__device__ float g_scal  [4];            // [0]=sum(h^2), [1]=1/denom

// ---------------------------------------------------------------------------
// Utility kernels
// ---------------------------------------------------------------------------
__global__ void k_zero(float* p, int n) {
    int i = blockIdx.x * blockDim.x + threadIdx.x;
    if (i < n) p[i] = 0.0f;
}

__global__ void k_deg_init(float* d, int n) {
    int i = blockIdx.x * blockDim.x + threadIdx.x;
    if (i < n) d[i] = 1.0f;                    // self-loop contributes 1
}

__global__ void k_deg_edges(float* d, const int* __restrict__ dst, int E) {
    int i = blockIdx.x * blockDim.x + threadIdx.x;
    if (i < E) atomicAdd(&d[dst[i]], 1.0f);
}

__global__ void k_deg_fin(float* d, int n) {
    int i = blockIdx.x * blockDim.x + threadIdx.x;
    if (i < n) d[i] = rsqrtf(d[i]);
}

// ---------------------------------------------------------------------------
// SGEMM: C[M,N] = A[M,K] * B[K,N], row-major. BM=BN=128, BK=8, 8x8 per thread.
// ---------------------------------------------------------------------------
__global__ __launch_bounds__(256) void k_sgemm(
    const float* __restrict__ A, const float* __restrict__ B,
    float* __restrict__ C, int M, int N, int K)
{
    const int BK = 8;
    __shared__ float As[8][128];
    __shared__ float Bs[8][128];

    int tid  = threadIdx.x;
    int cRow = blockIdx.y * 128;
    int cCol = blockIdx.x * 128;
    int tx = tid & 15;       // 0..15  (col groups of 8)
    int ty = tid >> 4;       // 0..15  (row groups of 8)

    float acc[8][8];
    #pragma unroll
    for (int m = 0; m < 8; m++)
        #pragma unroll
        for (int n = 0; n < 8; n++) acc[m][n] = 0.0f;

    // A tile loader: 128x8 floats, one float4 per thread
    int aR = tid >> 1;            // 0..127
    int aC = (tid & 1) * 4;       // 0 or 4
    // B tile loader: 8x128 floats, one float4 per thread
    int bR = tid >> 5;            // 0..7
    int bC = (tid & 31) * 4;      // 0..124

    bool aRowOk = (cRow + aR) < M;
    const float* aBase = A + (long long)(cRow + aR) * K;

    for (int k0 = 0; k0 < K; k0 += BK) {
        float4 av = make_float4(0.f, 0.f, 0.f, 0.f);
        if (aRowOk) {
            int kb = k0 + aC;
            if (kb + 3 < K) {
                av = *reinterpret_cast<const float4*>(aBase + kb);
            } else {
                float t[4] = {0.f, 0.f, 0.f, 0.f};
                #pragma unroll
                for (int q = 0; q < 4; q++) if (kb + q < K) t[q] = aBase[kb + q];
                av = make_float4(t[0], t[1], t[2], t[3]);
            }
        }
        As[aC + 0][aR] = av.x; As[aC + 1][aR] = av.y;
        As[aC + 2][aR] = av.z; As[aC + 3][aR] = av.w;

        float4 bv = make_float4(0.f, 0.f, 0.f, 0.f);
        int kr = k0 + bR;
        if (kr < K)
            bv = *reinterpret_cast<const float4*>(B + (long long)kr * N + cCol + bC);
        *reinterpret_cast<float4*>(&Bs[bR][bC]) = bv;

        __syncthreads();

        #pragma unroll
        for (int k = 0; k < BK; k++) {
            float ra[8], rb[8];
            #pragma unroll
            for (int m = 0; m < 8; m++) ra[m] = As[k][ty * 8 + m];
            #pragma unroll
            for (int n = 0; n < 8; n++) rb[n] = Bs[k][tx * 8 + n];
            #pragma unroll
            for (int m = 0; m < 8; m++)
                #pragma unroll
                for (int n = 0; n < 8; n++) acc[m][n] += ra[m] * rb[n];
        }
        __syncthreads();
    }

    #pragma unroll
    for (int m = 0; m < 8; m++) {
        int r = cRow + ty * 8 + m;
        if (r < M) {
            float* cBase = C + (long long)r * N + cCol + tx * 8;
            *reinterpret_cast<float4*>(cBase + 0) =
                make_float4(acc[m][0], acc[m][1], acc[m][2], acc[m][3]);
            *reinterpret_cast<float4*>(cBase + 4) =
                make_float4(acc[m][4], acc[m][5], acc[m][6], acc[m][7]);
        }
    }
}

// ---------------------------------------------------------------------------
// agg[i,j] = b[j] + dinv[i]^2 * xw[i,j]    (self-loop + bias init)
// ---------------------------------------------------------------------------
__global__ void k_agg_init(const float* __restrict__ xw, const float* __restrict__ bias,
                           const float* __restrict__ dinv, float* __restrict__ agg,
                           long long total, int lgH, int Hmask)
{
    long long idx = (long long)blockIdx.x * blockDim.x + threadIdx.x;
    if (idx >= total) return;
    int i = (int)(idx >> lgH);
    int j = (int)(idx & Hmask);
    float di = dinv[i];
    agg[idx] = bias[j] + di * di * xw[idx];
}

// ---------------------------------------------------------------------------
// Edge aggregation: agg[dst] += dinv[src]*dinv[dst] * xw[src]
// One thread = one (edge, 4-column chunk).
// ---------------------------------------------------------------------------
__global__ void k_edge_agg(const float4* __restrict__ xw, float* __restrict__ agg,
                           const int* __restrict__ src, const int* __restrict__ dst,
                           const float* __restrict__ dinv,
                           long long total, int lgHq, int Hqmask, int H)
{
    long long idx = (long long)blockIdx.x * blockDim.x + threadIdx.x;
    if (idx >= total) return;
    int e  = (int)(idx >> lgHq);
    int j4 = (int)(idx & Hqmask);
    int s = src[e];
    int d = dst[e];
    float w = dinv[s] * dinv[d];
    float4 v = xw[(long long)s * (H >> 2) + j4];
    float* out = agg + (long long)d * H + j4 * 4;
    atomicAdd(out + 0, w * v.x);
    atomicAdd(out + 1, w * v.y);
    atomicAdd(out + 2, w * v.z);
    atomicAdd(out + 3, w * v.w);
}

// ---------------------------------------------------------------------------
// Column sum + sum-of-squares (2D grid: x over columns, y over row chunks)
// ---------------------------------------------------------------------------
__global__ void k_colstats(const float* __restrict__ h, float* __restrict__ colsum,
                           float* __restrict__ colsq, int n, int H, int rpb)
{
    int j = blockIdx.x * blockDim.x + threadIdx.x;
    if (j >= H) return;
    int r0 = blockIdx.y * rpb;
    int r1 = min(n, r0 + rpb);
    float s = 0.f, ss = 0.f;
    for (int r = r0; r < r1; r++) {
        float v = h[(long long)r * H + j];
        s += v; ss += v * v;
    }
    atomicAdd(&colsum[j], s);
    atomicAdd(&colsq[j], ss);
}

__global__ void k_bnfin(const float* __restrict__ colsum, const float* __restrict__ colsq,
                        const float* __restrict__ gam, const float* __restrict__ bet,
                        float* __restrict__ scale, float* __restrict__ shift, int n, int H)
{
    int j = blockIdx.x * blockDim.x + threadIdx.x;
    if (j >= H) return;
    float invn = 1.0f / (float)n;
    float m   = colsum[j] * invn;
    float var = colsq[j] * invn - m * m;
    float sc  = gam[j] * rsqrtf(var + 1e-5f);
    scale[j] = sc;
    shift[j] = bet[j] - m * sc;
}

// ---------------------------------------------------------------------------
// h = relu(agg*scale+shift); accumulate column sums (pairnorm mean) and sum(h^2)
// ---------------------------------------------------------------------------
__global__ void k_bnrelu_pn(const float* __restrict__ agg, const float* __restrict__ scale,
                            const float* __restrict__ shift, float* __restrict__ h,
                            float* __restrict__ pnsum, float* __restrict__ sumsq,
                            int n, int H, int rpb)
{
    int j = blockIdx.x * blockDim.x + threadIdx.x;
    float s = 0.f, ss = 0.f;
    if (j < H) {
        float sc = scale[j], sh = shift[j];
        int r0 = blockIdx.y * rpb;
        int r1 = min(n, r0 + rpb);
        for (int r = r0; r < r1; r++) {
            long long o = (long long)r * H + j;
            float v = fmaxf(0.f, agg[o] * sc + sh);
            h[o] = v;
            s += v; ss += v * v;
        }
        atomicAdd(&pnsum[j], s);
    }
    __shared__ float red[256];
    red[threadIdx.x] = ss;
    __syncthreads();
    for (int st = 128; st > 0; st >>= 1) {
        if (threadIdx.x < st) red[threadIdx.x] += red[threadIdx.x + st];
        __syncthreads();
    }
    if (threadIdx.x == 0) atomicAdd(sumsq, red[0]);
}

// PairNorm finalize: pnmean[j] = colsum/n ; scal[1] = 1/(sqrt((sum h^2 - n*sum mean^2)/n)+eps)
__global__ void k_pnfin(const float* __restrict__ pnsum, float* __restrict__ pnmean,
                        float* __restrict__ scal, int n, int H)
{
    __shared__ float red[512];
    int j = threadIdx.x;
    float m = 0.f;
    if (j < H) {
        m = pnsum[j] / (float)n;
        pnmean[j] = m;
    }
    red[j] = m * m;
    __syncthreads();
    for (int st = 256; st > 0; st >>= 1) {
        if (j < st) red[j] += red[j + st];
        __syncthreads();
    }
    if (j == 0) {
        float msq  = red[0];
        float ssum = scal[0];
        float denom = sqrtf(fmaxf(0.f, (ssum - (float)n * msq) / (float)n)) + 1e-12f;
        scal[1] = 1.0f / denom;
    }
}

// out[i,j] = (h[i,j]-pnmean[j])*invd + p[i,j] + pb[j]
__global__ void k_combine(const float* __restrict__ h, const float* __restrict__ pnmean,
                          const float* __restrict__ scal, const float* __restrict__ p,
                          const float* __restrict__ pb, float* __restrict__ out,
                          long long total, int Hmask)
{
    long long idx = (long long)blockIdx.x * blockDim.x + threadIdx.x;
    if (idx >= total) return;
    int j = (int)(idx & Hmask);
    float invd = scal[1];
    out[idx] = (h[idx] - pnmean[j]) * invd + p[idx] + pb[j];
}

// ---------------------------------------------------------------------------
// Host side
// ---------------------------------------------------------------------------
static inline int cdiv_ll(long long a, long long b) { return (int)((a + b - 1) / b); }
static inline int ilog2(int x) { int l = 0; while ((1 << l) < x) l++; return l; }

extern "C" void kernel_launch(void* const* d_in, const int* in_sizes, int n_in,
                              void* d_out, int out_size)
{
    const float* x   = (const float*)d_in[0];
    const int*   ei  = (const int*)  d_in[1];
    const float* W1  = (const float*)d_in[2];
    const float* b1  = (const float*)d_in[3];
    const float* gm1 = (const float*)d_in[4];
    const float* be1 = (const float*)d_in[5];
    const float* W2  = (const float*)d_in[6];
    const float* b2  = (const float*)d_in[7];
    const float* gm2 = (const float*)d_in[8];
    const float* be2 = (const float*)d_in[9];
    const float* P1w = (const float*)d_in[10];
    const float* P1b = (const float*)d_in[11];
    const float* P2w = (const float*)d_in[12];
    const float* P2b = (const float*)d_in[13];

    const int H1 = in_sizes[3];
    const int H2 = in_sizes[7];
    const int IN = in_sizes[2] / H1;
    const int Nn = in_sizes[0] / IN;
    const int E  = in_sizes[1] / 2;
    const int* src = ei;
    const int* dst = ei + E;
    float* out = (float*)d_out;

    float *bufA, *bufB, *bufC, *dinv;
    float *colsum, *colsq, *scale, *shift, *pnsum, *pnmean, *scal;
    cudaGetSymbolAddress((void**)&bufA,  g_bufA);
    cudaGetSymbolAddress((void**)&bufB,  g_bufB);
    cudaGetSymbolAddress((void**)&bufC,  g_bufC);
    cudaGetSymbolAddress((void**)&dinv,  g_dinv);
    cudaGetSymbolAddress((void**)&colsum,g_colsum);
    cudaGetSymbolAddress((void**)&colsq, g_colsq);
    cudaGetSymbolAddress((void**)&scale, g_scale);
    cudaGetSymbolAddress((void**)&shift, g_shift);
    cudaGetSymbolAddress((void**)&pnsum, g_pnsum);
    cudaGetSymbolAddress((void**)&pnmean,g_pnmean);
    cudaGetSymbolAddress((void**)&scal,  g_scal);

    const int T = 256;

    // ---- degrees ----
    k_deg_init <<<cdiv_ll(Nn, T), T>>>(dinv, Nn);
    k_deg_edges<<<cdiv_ll(E,  T), T>>>(dinv, dst, E);
    k_deg_fin  <<<cdiv_ll(Nn, T), T>>>(dinv, Nn);

    const int GY = 200;                       // row-chunk blocks for column stats
    const int RPB = (Nn + GY - 1) / GY;

    // ================= Layer 1 =================
    // xw1 = bufA, p1 = bufB, agg1 = bufC; h(relu) -> bufA; h1 -> bufC
    {
        float* xw1  = bufA;
        float* p1   = bufB;
        float* agg1 = bufC;

        dim3 gg(H1 / 128, cdiv_ll(Nn, 128));
        k_sgemm<<<gg, T>>>(x, W1,  xw1, Nn, H1, IN);
        k_sgemm<<<gg, T>>>(x, P1w, p1,  Nn, H1, IN);

        long long tot = (long long)Nn * H1;
        int lgH = ilog2(H1);
        k_agg_init<<<cdiv_ll(tot, T), T>>>(xw1, b1, dinv, agg1, tot, lgH, H1 - 1);

        int Hq = H1 >> 2;
        long long etot = (long long)E * Hq;
        k_edge_agg<<<cdiv_ll(etot, T), T>>>((const float4*)xw1, agg1, src, dst, dinv,
                                            etot, ilog2(Hq), Hq - 1, H1);

        k_zero<<<cdiv_ll(H1, T), T>>>(colsum, H1);
        k_zero<<<cdiv_ll(H1, T), T>>>(colsq,  H1);
        k_zero<<<cdiv_ll(H1, T), T>>>(pnsum,  H1);
        k_zero<<<1, 32>>>(scal, 4);

        dim3 gs(cdiv_ll(H1, T), GY);
        k_colstats<<<gs, T>>>(agg1, colsum, colsq, Nn, H1, RPB);
        k_bnfin<<<cdiv_ll(H1, T), T>>>(colsum, colsq, gm1, be1, scale, shift, Nn, H1);
        // relu(bn(agg1)) -> bufA (xw1 no longer needed)
        k_bnrelu_pn<<<gs, T>>>(agg1, scale, shift, xw1, pnsum, scal, Nn, H1, RPB);
        k_pnfin<<<1, 512>>>(pnsum, pnmean, scal, Nn, H1);
        // h1 = pairnorm(bufA) + p1 + P1b -> bufC (agg1 no longer needed)
        k_combine<<<cdiv_ll(tot, T), T>>>(xw1, pnmean, scal, p1, P1b, agg1, tot, H1 - 1);
    }

    // ================= Layer 2 =================
    // h1 lives in bufC. xw2 = bufA[0 : N*H2), agg2 = bufA[N*H2 : 2*N*H2), p2 = bufB.
    {
        float* h1   = bufC;
        float* xw2  = bufA;
        float* agg2 = bufA + (long long)MAXN * MAXH2;
        float* p2   = bufB;

        dim3 gg(H2 / 128, cdiv_ll(Nn, 128));
        k_sgemm<<<gg, T>>>(h1, W2,  xw2, Nn, H2, H1);
        k_sgemm<<<gg, T>>>(h1, P2w, p2,  Nn, H2, H1);

        long long tot = (long long)Nn * H2;
        int lgH = ilog2(H2);
        k_agg_init<<<cdiv_ll(tot, T), T>>>(xw2, b2, dinv, agg2, tot, lgH, H2 - 1);

        int Hq = H2 >> 2;
        long long etot = (long long)E * Hq;
        k_edge_agg<<<cdiv_ll(etot, T), T>>>((const float4*)xw2, agg2, src, dst, dinv,
                                            etot, ilog2(Hq), Hq - 1, H2);

        k_zero<<<cdiv_ll(H2, T), T>>>(colsum, H2);
        k_zero<<<cdiv_ll(H2, T), T>>>(colsq,  H2);
        k_zero<<<cdiv_ll(H2, T), T>>>(pnsum,  H2);
        k_zero<<<1, 32>>>(scal, 4);

        dim3 gs(cdiv_ll(H2, T), GY);
        k_colstats<<<gs, T>>>(agg2, colsum, colsq, Nn, H2, RPB);
        k_bnfin<<<cdiv_ll(H2, T), T>>>(colsum, colsq, gm2, be2, scale, shift, Nn, H2);
        // relu(bn(agg2)) -> xw2 region (distinct from agg2 region)
        k_bnrelu_pn<<<gs, T>>>(agg2, scale, shift, xw2, pnsum, scal, Nn, H2, RPB);
        k_pnfin<<<1, 512>>>(pnsum, pnmean, scal, Nn, H2);
        k_combine<<<cdiv_ll(tot, T), T>>>(xw2, pnmean, scal, p2, P2b, out, tot, H2 - 1);
    }
}

// round 5
// speedup vs baseline: 1.0216x; 1.0216x over previous
#include <cuda_runtime.h>
#include <math.h>

// ---------------------------------------------------------------------------
// Shapes (reference: N=50000, IN=500, H1=512, H2=256)
// ---------------------------------------------------------------------------
#define MAXN  50048
#define MAXH1 512
#define MAXH2 256

// Scratch: three N x H1 buffers with lifetime aliasing (layer-2 sub-buffers
// live inside them). ~308 MB total static device memory.
__device__ float g_bufA[MAXN * MAXH1];
__device__ float g_bufB[MAXN * MAXH1];
__device__ float g_bufC[MAXN * MAXH1];
__device__ float g_dinv[MAXN];
__device__ float g_colsum[MAXH1];
__device__ float g_colsq [MAXH1];
__device__ float g_scale [MAXH1];
__device__ float g_shift [MAXH1];
__device__ float g_pnsum [MAXH1];
__device__ float g_pnmean[MAXH1];
__device__ float g_scal  [4];            // [0]=sum(h^2), [1]=1/denom

// ---------------------------------------------------------------------------
// Utility kernels
// ---------------------------------------------------------------------------
__global__ void k_zero(float* p, int n) {
    int i = blockIdx.x * blockDim.x + threadIdx.x;
    if (i < n) p[i] = 0.0f;
}

__global__ void k_deg_init(float* d, int n) {
    int i = blockIdx.x * blockDim.x + threadIdx.x;
    if (i < n) d[i] = 1.0f;                    // self-loop contributes 1
}

__global__ void k_deg_edges(float* d, const int* __restrict__ dst, int E) {
    int i = blockIdx.x * blockDim.x + threadIdx.x;
    if (i < E) atomicAdd(&d[dst[i]], 1.0f);
}

__global__ void k_deg_fin(float* d, int n) {
    int i = blockIdx.x * blockDim.x + threadIdx.x;
    if (i < n) d[i] = rsqrtf(d[i]);
}

// ---------------------------------------------------------------------------
// SGEMM: C[M,N] = A[M,K] * B[K,N], row-major. BM=BN=128, BK=8, 8x8 per thread.
// Double-buffered shared tiles, register-staged inner product.
// Same signature / launch shape as the round-2 passing version.
// ---------------------------------------------------------------------------
__global__ __launch_bounds__(256) void k_sgemm(
    const float* __restrict__ A, const float* __restrict__ B,
    float* __restrict__ C, int M, int N, int K)
{
    __shared__ float As[2][8][128];
    __shared__ float Bs[2][8][128];

    int tid  = threadIdx.x;
    int cRow = blockIdx.y * 128;
    int cCol = blockIdx.x * 128;
    int tx = tid & 15;       // 0..15  (col groups of 8)
    int ty = tid >> 4;       // 0..15  (row groups of 8)

    float acc[8][8];
    #pragma unroll
    for (int m = 0; m < 8; m++)
        #pragma unroll
        for (int n = 0; n < 8; n++) acc[m][n] = 0.0f;

    // A tile loader: 128x8 floats, one float4 per thread
    int aR = tid >> 1;            // 0..127
    int aC = (tid & 1) * 4;       // 0 or 4
    // B tile loader: 8x128 floats, one float4 per thread
    int bR = tid >> 5;            // 0..7
    int bC = (tid & 31) * 4;      // 0..124

    bool aRowOk = (cRow + aR) < M;
    const float* aBase = A + (long long)(cRow + aR) * K;
    const float* bBase = B + cCol + bC;

    int nIter = (K + 7) >> 3;

    // ---- preload tile 0 ----
    {
        float4 av = make_float4(0.f, 0.f, 0.f, 0.f);
        if (aRowOk && aC < K) {
            if (aC + 3 < K) {
                av = *reinterpret_cast<const float4*>(aBase + aC);
            } else {
                float t[4] = {0.f, 0.f, 0.f, 0.f};
                #pragma unroll
                for (int q = 0; q < 4; q++) if (aC + q < K) t[q] = aBase[aC + q];
                av = make_float4(t[0], t[1], t[2], t[3]);
            }
        }
        As[0][aC + 0][aR] = av.x; As[0][aC + 1][aR] = av.y;
        As[0][aC + 2][aR] = av.z; As[0][aC + 3][aR] = av.w;

        float4 bv = make_float4(0.f, 0.f, 0.f, 0.f);
        if (bR < K)
            bv = *reinterpret_cast<const float4*>(bBase + (long long)bR * N);
        *reinterpret_cast<float4*>(&Bs[0][bR][bC]) = bv;
    }
    __syncthreads();

    int buf = 0;
    for (int it = 0; it < nIter; it++) {
        bool more = (it + 1) < nIter;
        float4 av = make_float4(0.f, 0.f, 0.f, 0.f);
        float4 bv = make_float4(0.f, 0.f, 0.f, 0.f);
        if (more) {
            int kb = (it + 1) * 8 + aC;
            if (aRowOk && kb < K) {
                if (kb + 3 < K) {
                    av = *reinterpret_cast<const float4*>(aBase + kb);
                } else {
                    float t[4] = {0.f, 0.f, 0.f, 0.f};
                    #pragma unroll
                    for (int q = 0; q < 4; q++) if (kb + q < K) t[q] = aBase[kb + q];
                    av = make_float4(t[0], t[1], t[2], t[3]);
                }
            }
            int kr = (it + 1) * 8 + bR;
            if (kr < K)
                bv = *reinterpret_cast<const float4*>(bBase + (long long)kr * N);
        }

        #pragma unroll
        for (int k = 0; k < 8; k++) {
            float4 a0 = *reinterpret_cast<const float4*>(&As[buf][k][ty * 8]);
            float4 a1 = *reinterpret_cast<const float4*>(&As[buf][k][ty * 8 + 4]);
            float4 b0 = *reinterpret_cast<const float4*>(&Bs[buf][k][tx * 8]);
            float4 b1 = *reinterpret_cast<const float4*>(&Bs[buf][k][tx * 8 + 4]);
            float ra[8] = {a0.x, a0.y, a0.z, a0.w, a1.x, a1.y, a1.z, a1.w};
            float rb[8] = {b0.x, b0.y, b0.z, b0.w, b1.x, b1.y, b1.z, b1.w};
            #pragma unroll
            for (int m = 0; m < 8; m++)
                #pragma unroll
                for (int n = 0; n < 8; n++) acc[m][n] += ra[m] * rb[n];
        }

        if (more) {
            int nb = buf ^ 1;
            As[nb][aC + 0][aR] = av.x; As[nb][aC + 1][aR] = av.y;
            As[nb][aC + 2][aR] = av.z; As[nb][aC + 3][aR] = av.w;
            *reinterpret_cast<float4*>(&Bs[nb][bR][bC]) = bv;
            __syncthreads();
            buf = nb;
        }
    }

    #pragma unroll
    for (int m = 0; m < 8; m++) {
        int r = cRow + ty * 8 + m;
        if (r < M) {
            float* cBase = C + (long long)r * N + cCol + tx * 8;
            *reinterpret_cast<float4*>(cBase + 0) =
                make_float4(acc[m][0], acc[m][1], acc[m][2], acc[m][3]);
            *reinterpret_cast<float4*>(cBase + 4) =
                make_float4(acc[m][4], acc[m][5], acc[m][6], acc[m][7]);
        }
    }
}

// ---------------------------------------------------------------------------
// agg[i,j] = b[j] + dinv[i]^2 * xw[i,j]    (self-loop + bias init)
// ---------------------------------------------------------------------------
__global__ void k_agg_init(const float* __restrict__ xw, const float* __restrict__ bias,
                           const float* __restrict__ dinv, float* __restrict__ agg,
                           long long total, int lgH, int Hmask)
{
    long long idx = (long long)blockIdx.x * blockDim.x + threadIdx.x;
    if (idx >= total) return;
    int i = (int)(idx >> lgH);
    int j = (int)(idx & Hmask);
    float di = dinv[i];
    agg[idx] = bias[j] + di * di * xw[idx];
}

// ---------------------------------------------------------------------------
// Edge aggregation: agg[dst] += dinv[src]*dinv[dst] * xw[src]
// One thread = one (edge, 4-column chunk).
// ---------------------------------------------------------------------------
__global__ void k_edge_agg(const float4* __restrict__ xw, float* __restrict__ agg,
                           const int* __restrict__ src, const int* __restrict__ dst,
                           const float* __restrict__ dinv,
                           long long total, int lgHq, int Hqmask, int H)
{
    long long idx = (long long)blockIdx.x * blockDim.x + threadIdx.x;
    if (idx >= total) return;
    int e  = (int)(idx >> lgHq);
    int j4 = (int)(idx & Hqmask);
    int s = src[e];
    int d = dst[e];
    float w = dinv[s] * dinv[d];
    float4 v = xw[(long long)s * (H >> 2) + j4];
    float* out = agg + (long long)d * H + j4 * 4;
    atomicAdd(out + 0, w * v.x);
    atomicAdd(out + 1, w * v.y);
    atomicAdd(out + 2, w * v.z);
    atomicAdd(out + 3, w * v.w);
}

// ---------------------------------------------------------------------------
// Column sum + sum-of-squares (2D grid: x over columns, y over row chunks)
// ---------------------------------------------------------------------------
__global__ void k_colstats(const float* __restrict__ h, float* __restrict__ colsum,
                           float* __restrict__ colsq, int n, int H, int rpb)
{
    int j = blockIdx.x * blockDim.x + threadIdx.x;
    if (j >= H) return;
    int r0 = blockIdx.y * rpb;
    int r1 = min(n, r0 + rpb);
    float s = 0.f, ss = 0.f;
    for (int r = r0; r < r1; r++) {
        float v = h[(long long)r * H + j];
        s += v; ss += v * v;
    }
    atomicAdd(&colsum[j], s);
    atomicAdd(&colsq[j], ss);
}

__global__ void k_bnfin(const float* __restrict__ colsum, const float* __restrict__ colsq,
                        const float* __restrict__ gam, const float* __restrict__ bet,
                        float* __restrict__ scale, float* __restrict__ shift, int n, int H)
{
    int j = blockIdx.x * blockDim.x + threadIdx.x;
    if (j >= H) return;
    float invn = 1.0f / (float)n;
    float m   = colsum[j] * invn;
    float var = colsq[j] * invn - m * m;
    float sc  = gam[j] * rsqrtf(var + 1e-5f);
    scale[j] = sc;
    shift[j] = bet[j] - m * sc;
}

// ---------------------------------------------------------------------------
// h = relu(agg*scale+shift); accumulate column sums (pairnorm mean) and sum(h^2)
// ---------------------------------------------------------------------------
__global__ void k_bnrelu_pn(const float* __restrict__ agg, const float* __restrict__ scale,
                            const float* __restrict__ shift, float* __restrict__ h,
                            float* __restrict__ pnsum, float* __restrict__ sumsq,
                            int n, int H, int rpb)
{
    int j = blockIdx.x * blockDim.x + threadIdx.x;
    float s = 0.f, ss = 0.f;
    if (j < H) {
        float sc = scale[j], sh = shift[j];
        int r0 = blockIdx.y * rpb;
        int r1 = min(n, r0 + rpb);
        for (int r = r0; r < r1; r++) {
            long long o = (long long)r * H + j;
            float v = fmaxf(0.f, agg[o] * sc + sh);
            h[o] = v;
            s += v; ss += v * v;
        }
        atomicAdd(&pnsum[j], s);
    }
    __shared__ float red[256];
    red[threadIdx.x] = ss;
    __syncthreads();
    for (int st = 128; st > 0; st >>= 1) {
        if (threadIdx.x < st) red[threadIdx.x] += red[threadIdx.x + st];
        __syncthreads();
    }
    if (threadIdx.x == 0) atomicAdd(sumsq, red[0]);
}

// PairNorm finalize
__global__ void k_pnfin(const float* __restrict__ pnsum, float* __restrict__ pnmean,
                        float* __restrict__ scal, int n, int H)
{
    __shared__ float red[512];
    int j = threadIdx.x;
    float m = 0.f;
    if (j < H) {
        m = pnsum[j] / (float)n;
        pnmean[j] = m;
    }
    red[j] = m * m;
    __syncthreads();
    for (int st = 256; st > 0; st >>= 1) {
        if (j < st) red[j] += red[j + st];
        __syncthreads();
    }
    if (j == 0) {
        float msq  = red[0];
        float ssum = scal[0];
        float denom = sqrtf(fmaxf(0.f, (ssum - (float)n * msq) / (float)n)) + 1e-12f;
        scal[1] = 1.0f / denom;
    }
}

// out[i,j] = (h[i,j]-pnmean[j])*invd + p[i,j] + pb[j]
__global__ void k_combine(const float* __restrict__ h, const float* __restrict__ pnmean,
                          const float* __restrict__ scal, const float* __restrict__ p,
                          const float* __restrict__ pb, float* __restrict__ out,
                          long long total, int Hmask)
{
    long long idx = (long long)blockIdx.x * blockDim.x + threadIdx.x;
    if (idx >= total) return;
    int j = (int)(idx & Hmask);
    float invd = scal[1];
    out[idx] = (h[idx] - pnmean[j]) * invd + p[idx] + pb[j];
}

// ---------------------------------------------------------------------------
// Host side
// ---------------------------------------------------------------------------
static inline int cdiv_ll(long long a, long long b) { return (int)((a + b - 1) / b); }
static inline int ilog2(int x) { int l = 0; while ((1 << l) < x) l++; return l; }

extern "C" void kernel_launch(void* const* d_in, const int* in_sizes, int n_in,
                              void* d_out, int out_size)
{
    const float* x   = (const float*)d_in[0];
    const int*   ei  = (const int*)  d_in[1];
    const float* W1  = (const float*)d_in[2];
    const float* b1  = (const float*)d_in[3];
    const float* gm1 = (const float*)d_in[4];
    const float* be1 = (const float*)d_in[5];
    const float* W2  = (const float*)d_in[6];
    const float* b2  = (const float*)d_in[7];
    const float* gm2 = (const float*)d_in[8];
    const float* be2 = (const float*)d_in[9];
    const float* P1w = (const float*)d_in[10];
    const float* P1b = (const float*)d_in[11];
    const float* P2w = (const float*)d_in[12];
    const float* P2b = (const float*)d_in[13];

    const int H1 = in_sizes[3];
    const int H2 = in_sizes[7];
    const int IN = in_sizes[2] / H1;
    const int Nn = in_sizes[0] / IN;
    const int E  = in_sizes[1] / 2;
    const int* src = ei;
    const int* dst = ei + E;
    float* out = (float*)d_out;

    float *bufA, *bufB, *bufC, *dinv;
    float *colsum, *colsq, *scale, *shift, *pnsum, *pnmean, *scal;
    cudaGetSymbolAddress((void**)&bufA,  g_bufA);
    cudaGetSymbolAddress((void**)&bufB,  g_bufB);
    cudaGetSymbolAddress((void**)&bufC,  g_bufC);
    cudaGetSymbolAddress((void**)&dinv,  g_dinv);
    cudaGetSymbolAddress((void**)&colsum,g_colsum);
    cudaGetSymbolAddress((void**)&colsq, g_colsq);
    cudaGetSymbolAddress((void**)&scale, g_scale);
    cudaGetSymbolAddress((void**)&shift, g_shift);
    cudaGetSymbolAddress((void**)&pnsum, g_pnsum);
    cudaGetSymbolAddress((void**)&pnmean,g_pnmean);
    cudaGetSymbolAddress((void**)&scal,  g_scal);

    const int T = 256;

    // ---- degrees ----
    k_deg_init <<<cdiv_ll(Nn, T), T>>>(dinv, Nn);
    k_deg_edges<<<cdiv_ll(E,  T), T>>>(dinv, dst, E);
    k_deg_fin  <<<cdiv_ll(Nn, T), T>>>(dinv, Nn);

    const int GY = 200;                       // row-chunk blocks for column stats
    const int RPB = (Nn + GY - 1) / GY;

    // ================= Layer 1 =================
    // xw1 = bufA, p1 = bufB, agg1 = bufC; h(relu) -> bufA; h1 -> bufC
    {
        float* xw1  = bufA;
        float* p1   = bufB;
        float* agg1 = bufC;

        dim3 gg(H1 / 128, cdiv_ll(Nn, 128));
        k_sgemm<<<gg, T>>>(x, W1,  xw1, Nn, H1, IN);
        k_sgemm<<<gg, T>>>(x, P1w, p1,  Nn, H1, IN);

        long long tot = (long long)Nn * H1;
        int lgH = ilog2(H1);
        k_agg_init<<<cdiv_ll(tot, T), T>>>(xw1, b1, dinv, agg1, tot, lgH, H1 - 1);

        int Hq = H1 >> 2;
        long long etot = (long long)E * Hq;
        k_edge_agg<<<cdiv_ll(etot, T), T>>>((const float4*)xw1, agg1, src, dst, dinv,
                                            etot, ilog2(Hq), Hq - 1, H1);

        k_zero<<<cdiv_ll(H1, T), T>>>(colsum, H1);
        k_zero<<<cdiv_ll(H1, T), T>>>(colsq,  H1);
        k_zero<<<cdiv_ll(H1, T), T>>>(pnsum,  H1);
        k_zero<<<1, 32>>>(scal, 4);

        dim3 gs(cdiv_ll(H1, T), GY);
        k_colstats<<<gs, T>>>(agg1, colsum, colsq, Nn, H1, RPB);
        k_bnfin<<<cdiv_ll(H1, T), T>>>(colsum, colsq, gm1, be1, scale, shift, Nn, H1);
        // relu(bn(agg1)) -> bufA (xw1 no longer needed)
        k_bnrelu_pn<<<gs, T>>>(agg1, scale, shift, xw1, pnsum, scal, Nn, H1, RPB);
        k_pnfin<<<1, 512>>>(pnsum, pnmean, scal, Nn, H1);
        // h1 = pairnorm(bufA) + p1 + P1b -> bufC (agg1 no longer needed)
        k_combine<<<cdiv_ll(tot, T), T>>>(xw1, pnmean, scal, p1, P1b, agg1, tot, H1 - 1);
    }

    // ================= Layer 2 =================
    // h1 lives in bufC. xw2 = bufA[0 : N*H2), agg2 = bufA[N*H2 : 2*N*H2), p2 = bufB.
    {
        float* h1   = bufC;
        float* xw2  = bufA;
        float* agg2 = bufA + (long long)MAXN * MAXH2;
        float* p2   = bufB;

        dim3 gg(H2 / 128, cdiv_ll(Nn, 128));
        k_sgemm<<<gg, T>>>(h1, W2,  xw2, Nn, H2, H1);
        k_sgemm<<<gg, T>>>(h1, P2w, p2,  Nn, H2, H1);

        long long tot = (long long)Nn * H2;
        int lgH = ilog2(H2);
        k_agg_init<<<cdiv_ll(tot, T), T>>>(xw2, b2, dinv, agg2, tot, lgH, H2 - 1);

        int Hq = H2 >> 2;
        long long etot = (long long)E * Hq;
        k_edge_agg<<<cdiv_ll(etot, T), T>>>((const float4*)xw2, agg2, src, dst, dinv,
                                            etot, ilog2(Hq), Hq - 1, H2);

        k_zero<<<cdiv_ll(H2, T), T>>>(colsum, H2);
        k_zero<<<cdiv_ll(H2, T), T>>>(colsq,  H2);
        k_zero<<<cdiv_ll(H2, T), T>>>(pnsum,  H2);
        k_zero<<<1, 32>>>(scal, 4);

        dim3 gs(cdiv_ll(H2, T), GY);
        k_colstats<<<gs, T>>>(agg2, colsum, colsq, Nn, H2, RPB);
        k_bnfin<<<cdiv_ll(H2, T), T>>>(colsum, colsq, gm2, be2, scale, shift, Nn, H2);
        // relu(bn(agg2)) -> xw2 region (distinct from agg2 region)
        k_bnrelu_pn<<<gs, T>>>(agg2, scale, shift, xw2, pnsum, scal, Nn, H2, RPB);
        k_pnfin<<<1, 512>>>(pnsum, pnmean, scal, Nn, H2);
        k_combine<<<cdiv_ll(tot, T), T>>>(xw2, pnmean, scal, p2, P2b, out, tot, H2 - 1);
    }
}

// round 6
// speedup vs baseline: 1.5149x; 1.4829x over previous
#include <cuda_runtime.h>
#include <math.h>

// ---------------------------------------------------------------------------
// Shapes (reference: N=50000, IN=500, H1=512, H2=256, E=800000)
// ---------------------------------------------------------------------------
#define MAXN  50048
#define MAXH1 512
#define MAXH2 256
#define MAXE  800000

// Scratch (~310 MB static device memory, lifetime-aliased)
__device__ float g_bufA[MAXN * MAXH1];
__device__ float g_bufB[MAXN * MAXH1];
__device__ float g_bufC[MAXN * MAXH1];
__device__ float g_dinv[MAXN];
__device__ int   g_cnt   [MAXN];
__device__ int   g_start [MAXN + 1];
__device__ int   g_cursor[MAXN];
__device__ int   g_srcs  [MAXE];
__device__ float g_colsum[MAXH1];
__device__ float g_colsq [MAXH1];
__device__ float g_scale [MAXH1];
__device__ float g_shift [MAXH1];
__device__ float g_pnsum [MAXH1];
__device__ float g_pnmean[MAXH1];
__device__ float g_scal  [4];            // [0]=sum(h^2), [1]=1/denom

// ---------------------------------------------------------------------------
// Utility kernels
// ---------------------------------------------------------------------------
__global__ void k_zero(float* p, int n) {
    int i = blockIdx.x * blockDim.x + threadIdx.x;
    if (i < n) p[i] = 0.0f;
}

__global__ void k_zeroi(int* p, int n) {
    int i = blockIdx.x * blockDim.x + threadIdx.x;
    if (i < n) p[i] = 0;
}

// ---- CSR build ----
__global__ void k_count(int* cnt, const int* __restrict__ dst, int E) {
    int i = blockIdx.x * blockDim.x + threadIdx.x;
    if (i < E) atomicAdd(&cnt[dst[i]], 1);
}

// dinv[i] = rsqrt(1 + cnt[i])   (self-loop included)
__global__ void k_dinv(const int* __restrict__ cnt, float* dinv, int n) {
    int i = blockIdx.x * blockDim.x + threadIdx.x;
    if (i < n) dinv[i] = rsqrtf(1.0f + (float)cnt[i]);
}

// Single-block exclusive scan: start[0]=0, start[i+1]=sum(cnt[0..i])
__global__ void k_scan(const int* __restrict__ cnt, int* __restrict__ start, int n) {
    __shared__ int sh[1024];
    __shared__ int carrySh;
    int tid = threadIdx.x;
    if (tid == 0) { carrySh = 0; start[0] = 0; }
    __syncthreads();
    for (int base = 0; base < n; base += 1024) {
        int i = base + tid;
        int v = (i < n) ? cnt[i] : 0;
        sh[tid] = v;
        __syncthreads();
        for (int st = 1; st < 1024; st <<= 1) {
            int a = (tid >= st) ? sh[tid - st] : 0;
            __syncthreads();
            sh[tid] += a;
            __syncthreads();
        }
        int carry = carrySh;
        if (i < n) start[i + 1] = carry + sh[tid];
        __syncthreads();
        if (tid == 1023) carrySh = carry + sh[1023];
        __syncthreads();
    }
}

__global__ void k_copyi(const int* __restrict__ a, int* b, int n) {
    int i = blockIdx.x * blockDim.x + threadIdx.x;
    if (i < n) b[i] = a[i];
}

__global__ void k_scatter(const int* __restrict__ src, const int* __restrict__ dst,
                          int* cursor, int* __restrict__ srcs, int E) {
    int i = blockIdx.x * blockDim.x + threadIdx.x;
    if (i < E) {
        int d = dst[i];
        int pos = atomicAdd(&cursor[d], 1);
        srcs[pos] = src[i];
    }
}

// ---------------------------------------------------------------------------
// CSR gather aggregation (no atomics):
// agg[n,:] = bias + dinv[n]^2 * xw[n,:] + sum_{s in in(n)} dinv[s]*dinv[n]*xw[s,:]
// grid.x = N, blockDim = H/4 (<=128), each thread owns one float4 column chunk.
// ---------------------------------------------------------------------------
__global__ void k_csr_agg(const float4* __restrict__ xw,
                          const int* __restrict__ start, const int* __restrict__ srcs,
                          const float* __restrict__ dinv, const float* __restrict__ bias,
                          float4* __restrict__ agg, int Hq)
{
    int n = blockIdx.x;
    int t = threadIdx.x;
    float dn = dinv[n];
    float4 v = xw[(size_t)n * Hq + t];
    const float4* b4 = (const float4*)bias;
    float4 bb = b4[t];
    float w0 = dn * dn;
    float4 acc = make_float4(bb.x + w0 * v.x, bb.y + w0 * v.y,
                             bb.z + w0 * v.z, bb.w + w0 * v.w);
    int s0 = start[n], s1 = start[n + 1];
    for (int i = s0; i < s1; i++) {
        int s = srcs[i];
        float w = dinv[s] * dn;
        float4 u = xw[(size_t)s * Hq + t];
        acc.x += w * u.x; acc.y += w * u.y;
        acc.z += w * u.z; acc.w += w * u.w;
    }
    agg[(size_t)n * Hq + t] = acc;
}

// ---------------------------------------------------------------------------
// SGEMM: C[M,N] = A[M,K] * B[K,N], row-major. BM=BN=128, BK=8, 8x8 per thread.
// Double-buffered shared tiles, register-staged inner product. (R5-proven.)
// ---------------------------------------------------------------------------
__global__ __launch_bounds__(256) void k_sgemm(
    const float* __restrict__ A, const float* __restrict__ B,
    float* __restrict__ C, int M, int N, int K)
{
    __shared__ float As[2][8][128];
    __shared__ float Bs[2][8][128];

    int tid  = threadIdx.x;
    int cRow = blockIdx.y * 128;
    int cCol = blockIdx.x * 128;
    int tx = tid & 15;
    int ty = tid >> 4;

    float acc[8][8];
    #pragma unroll
    for (int m = 0; m < 8; m++)
        #pragma unroll
        for (int n = 0; n < 8; n++) acc[m][n] = 0.0f;

    int aR = tid >> 1;
    int aC = (tid & 1) * 4;
    int bR = tid >> 5;
    int bC = (tid & 31) * 4;

    bool aRowOk = (cRow + aR) < M;
    const float* aBase = A + (long long)(cRow + aR) * K;
    const float* bBase = B + cCol + bC;

    int nIter = (K + 7) >> 3;

    {
        float4 av = make_float4(0.f, 0.f, 0.f, 0.f);
        if (aRowOk && aC < K) {
            if (aC + 3 < K) {
                av = *reinterpret_cast<const float4*>(aBase + aC);
            } else {
                float t[4] = {0.f, 0.f, 0.f, 0.f};
                #pragma unroll
                for (int q = 0; q < 4; q++) if (aC + q < K) t[q] = aBase[aC + q];
                av = make_float4(t[0], t[1], t[2], t[3]);
            }
        }
        As[0][aC + 0][aR] = av.x; As[0][aC + 1][aR] = av.y;
        As[0][aC + 2][aR] = av.z; As[0][aC + 3][aR] = av.w;

        float4 bv = make_float4(0.f, 0.f, 0.f, 0.f);
        if (bR < K)
            bv = *reinterpret_cast<const float4*>(bBase + (long long)bR * N);
        *reinterpret_cast<float4*>(&Bs[0][bR][bC]) = bv;
    }
    __syncthreads();

    int buf = 0;
    for (int it = 0; it < nIter; it++) {
        bool more = (it + 1) < nIter;
        float4 av = make_float4(0.f, 0.f, 0.f, 0.f);
        float4 bv = make_float4(0.f, 0.f, 0.f, 0.f);
        if (more) {
            int kb = (it + 1) * 8 + aC;
            if (aRowOk && kb < K) {
                if (kb + 3 < K) {
                    av = *reinterpret_cast<const float4*>(aBase + kb);
                } else {
                    float t[4] = {0.f, 0.f, 0.f, 0.f};
                    #pragma unroll
                    for (int q = 0; q < 4; q++) if (kb + q < K) t[q] = aBase[kb + q];
                    av = make_float4(t[0], t[1], t[2], t[3]);
                }
            }
            int kr = (it + 1) * 8 + bR;
            if (kr < K)
                bv = *reinterpret_cast<const float4*>(bBase + (long long)kr * N);
        }

        #pragma unroll
        for (int k = 0; k < 8; k++) {
            float4 a0 = *reinterpret_cast<const float4*>(&As[buf][k][ty * 8]);
            float4 a1 = *reinterpret_cast<const float4*>(&As[buf][k][ty * 8 + 4]);
            float4 b0 = *reinterpret_cast<const float4*>(&Bs[buf][k][tx * 8]);
            float4 b1 = *reinterpret_cast<const float4*>(&Bs[buf][k][tx * 8 + 4]);
            float ra[8] = {a0.x, a0.y, a0.z, a0.w, a1.x, a1.y, a1.z, a1.w};
            float rb[8] = {b0.x, b0.y, b0.z, b0.w, b1.x, b1.y, b1.z, b1.w};
            #pragma unroll
            for (int m = 0; m < 8; m++)
                #pragma unroll
                for (int n = 0; n < 8; n++) acc[m][n] += ra[m] * rb[n];
        }

        if (more) {
            int nb = buf ^ 1;
            As[nb][aC + 0][aR] = av.x; As[nb][aC + 1][aR] = av.y;
            As[nb][aC + 2][aR] = av.z; As[nb][aC + 3][aR] = av.w;
            *reinterpret_cast<float4*>(&Bs[nb][bR][bC]) = bv;
            __syncthreads();
            buf = nb;
        }
    }

    #pragma unroll
    for (int m = 0; m < 8; m++) {
        int r = cRow + ty * 8 + m;
        if (r < M) {
            float* cBase = C + (long long)r * N + cCol + tx * 8;
            *reinterpret_cast<float4*>(cBase + 0) =
                make_float4(acc[m][0], acc[m][1], acc[m][2], acc[m][3]);
            *reinterpret_cast<float4*>(cBase + 4) =
                make_float4(acc[m][4], acc[m][5], acc[m][6], acc[m][7]);
        }
    }
}

// ---------------------------------------------------------------------------
// Column sum + sum-of-squares (2D grid: x over columns, y over row chunks)
// ---------------------------------------------------------------------------
__global__ void k_colstats(const float* __restrict__ h, float* __restrict__ colsum,
                           float* __restrict__ colsq, int n, int H, int rpb)
{
    int j = blockIdx.x * blockDim.x + threadIdx.x;
    if (j >= H) return;
    int r0 = blockIdx.y * rpb;
    int r1 = min(n, r0 + rpb);
    float s = 0.f, ss = 0.f;
    for (int r = r0; r < r1; r++) {
        float v = h[(long long)r * H + j];
        s += v; ss += v * v;
    }
    atomicAdd(&colsum[j], s);
    atomicAdd(&colsq[j], ss);
}

__global__ void k_bnfin(const float* __restrict__ colsum, const float* __restrict__ colsq,
                        const float* __restrict__ gam, const float* __restrict__ bet,
                        float* __restrict__ scale, float* __restrict__ shift, int n, int H)
{
    int j = blockIdx.x * blockDim.x + threadIdx.x;
    if (j >= H) return;
    float invn = 1.0f / (float)n;
    float m   = colsum[j] * invn;
    float var = colsq[j] * invn - m * m;
    float sc  = gam[j] * rsqrtf(var + 1e-5f);
    scale[j] = sc;
    shift[j] = bet[j] - m * sc;
}

// ---------------------------------------------------------------------------
// h = relu(agg*scale+shift); accumulate column sums (pairnorm mean) and sum(h^2)
// ---------------------------------------------------------------------------
__global__ void k_bnrelu_pn(const float* __restrict__ agg, const float* __restrict__ scale,
                            const float* __restrict__ shift, float* __restrict__ h,
                            float* __restrict__ pnsum, float* __restrict__ sumsq,
                            int n, int H, int rpb)
{
    int j = blockIdx.x * blockDim.x + threadIdx.x;
    float s = 0.f, ss = 0.f;
    if (j < H) {
        float sc = scale[j], sh = shift[j];
        int r0 = blockIdx.y * rpb;
        int r1 = min(n, r0 + rpb);
        for (int r = r0; r < r1; r++) {
            long long o = (long long)r * H + j;
            float v = fmaxf(0.f, agg[o] * sc + sh);
            h[o] = v;
            s += v; ss += v * v;
        }
        atomicAdd(&pnsum[j], s);
    }
    __shared__ float red[256];
    red[threadIdx.x] = ss;
    __syncthreads();
    for (int st = 128; st > 0; st >>= 1) {
        if (threadIdx.x < st) red[threadIdx.x] += red[threadIdx.x + st];
        __syncthreads();
    }
    if (threadIdx.x == 0) atomicAdd(sumsq, red[0]);
}

// PairNorm finalize
__global__ void k_pnfin(const float* __restrict__ pnsum, float* __restrict__ pnmean,
                        float* __restrict__ scal, int n, int H)
{
    __shared__ float red[512];
    int j = threadIdx.x;
    float m = 0.f;
    if (j < H) {
        m = pnsum[j] / (float)n;
        pnmean[j] = m;
    }
    red[j] = m * m;
    __syncthreads();
    for (int st = 256; st > 0; st >>= 1) {
        if (j < st) red[j] += red[j + st];
        __syncthreads();
    }
    if (j == 0) {
        float msq  = red[0];
        float ssum = scal[0];
        float denom = sqrtf(fmaxf(0.f, (ssum - (float)n * msq) / (float)n)) + 1e-12f;
        scal[1] = 1.0f / denom;
    }
}

// out[i,j] = (h[i,j]-pnmean[j])*invd + p[i,j] + pb[j]
__global__ void k_combine(const float* __restrict__ h, const float* __restrict__ pnmean,
                          const float* __restrict__ scal, const float* __restrict__ p,
                          const float* __restrict__ pb, float* __restrict__ out,
                          long long total, int Hmask)
{
    long long idx = (long long)blockIdx.x * blockDim.x + threadIdx.x;
    if (idx >= total) return;
    int j = (int)(idx & Hmask);
    float invd = scal[1];
    out[idx] = (h[idx] - pnmean[j]) * invd + p[idx] + pb[j];
}

// ---------------------------------------------------------------------------
// Host side
// ---------------------------------------------------------------------------
static inline int cdiv_ll(long long a, long long b) { return (int)((a + b - 1) / b); }

extern "C" void kernel_launch(void* const* d_in, const int* in_sizes, int n_in,
                              void* d_out, int out_size)
{
    const float* x   = (const float*)d_in[0];
    const int*   ei  = (const int*)  d_in[1];
    const float* W1  = (const float*)d_in[2];
    const float* b1  = (const float*)d_in[3];
    const float* gm1 = (const float*)d_in[4];
    const float* be1 = (const float*)d_in[5];
    const float* W2  = (const float*)d_in[6];
    const float* b2  = (const float*)d_in[7];
    const float* gm2 = (const float*)d_in[8];
    const float* be2 = (const float*)d_in[9];
    const float* P1w = (const float*)d_in[10];
    const float* P1b = (const float*)d_in[11];
    const float* P2w = (const float*)d_in[12];
    const float* P2b = (const float*)d_in[13];

    const int H1 = in_sizes[3];
    const int H2 = in_sizes[7];
    const int IN = in_sizes[2] / H1;
    const int Nn = in_sizes[0] / IN;
    const int E  = in_sizes[1] / 2;
    const int* src = ei;
    const int* dst = ei + E;
    float* out = (float*)d_out;

    float *bufA, *bufB, *bufC, *dinv;
    float *colsum, *colsq, *scale, *shift, *pnsum, *pnmean, *scal;
    int *cnt, *startp, *cursor, *srcs;
    cudaGetSymbolAddress((void**)&bufA,  g_bufA);
    cudaGetSymbolAddress((void**)&bufB,  g_bufB);
    cudaGetSymbolAddress((void**)&bufC,  g_bufC);
    cudaGetSymbolAddress((void**)&dinv,  g_dinv);
    cudaGetSymbolAddress((void**)&cnt,   g_cnt);
    cudaGetSymbolAddress((void**)&startp,g_start);
    cudaGetSymbolAddress((void**)&cursor,g_cursor);
    cudaGetSymbolAddress((void**)&srcs,  g_srcs);
    cudaGetSymbolAddress((void**)&colsum,g_colsum);
    cudaGetSymbolAddress((void**)&colsq, g_colsq);
    cudaGetSymbolAddress((void**)&scale, g_scale);
    cudaGetSymbolAddress((void**)&shift, g_shift);
    cudaGetSymbolAddress((void**)&pnsum, g_pnsum);
    cudaGetSymbolAddress((void**)&pnmean,g_pnmean);
    cudaGetSymbolAddress((void**)&scal,  g_scal);

    const int T = 256;

    // ---- CSR build + dinv ----
    k_zeroi  <<<cdiv_ll(Nn, T), T>>>(cnt, Nn);
    k_count  <<<cdiv_ll(E,  T), T>>>(cnt, dst, E);
    k_dinv   <<<cdiv_ll(Nn, T), T>>>(cnt, dinv, Nn);
    k_scan   <<<1, 1024>>>(cnt, startp, Nn);
    k_copyi  <<<cdiv_ll(Nn, T), T>>>(startp, cursor, Nn);
    k_scatter<<<cdiv_ll(E,  T), T>>>(src, dst, cursor, srcs, E);

    const int GY = 200;
    const int RPB = (Nn + GY - 1) / GY;

    // ================= Layer 1 =================
    {
        float* xw1  = bufA;
        float* p1   = bufB;
        float* agg1 = bufC;

        dim3 gg(H1 / 128, cdiv_ll(Nn, 128));
        k_sgemm<<<gg, T>>>(x, W1,  xw1, Nn, H1, IN);
        k_sgemm<<<gg, T>>>(x, P1w, p1,  Nn, H1, IN);

        long long tot = (long long)Nn * H1;
        int Hq = H1 >> 2;
        k_csr_agg<<<Nn, Hq>>>((const float4*)xw1, startp, srcs, dinv, b1,
                              (float4*)agg1, Hq);

        k_zero<<<cdiv_ll(H1, T), T>>>(colsum, H1);
        k_zero<<<cdiv_ll(H1, T), T>>>(colsq,  H1);
        k_zero<<<cdiv_ll(H1, T), T>>>(pnsum,  H1);
        k_zero<<<1, 32>>>(scal, 4);

        dim3 gs(cdiv_ll(H1, T), GY);
        k_colstats<<<gs, T>>>(agg1, colsum, colsq, Nn, H1, RPB);
        k_bnfin<<<cdiv_ll(H1, T), T>>>(colsum, colsq, gm1, be1, scale, shift, Nn, H1);
        k_bnrelu_pn<<<gs, T>>>(agg1, scale, shift, xw1, pnsum, scal, Nn, H1, RPB);
        k_pnfin<<<1, 512>>>(pnsum, pnmean, scal, Nn, H1);
        k_combine<<<cdiv_ll(tot, T), T>>>(xw1, pnmean, scal, p1, P1b, agg1, tot, H1 - 1);
    }

    // ================= Layer 2 =================
    // h1 lives in bufC. xw2 = bufA[0:N*H2), agg2 = bufA[N*H2:2N*H2), p2 = bufB.
    {
        float* h1   = bufC;
        float* xw2  = bufA;
        float* agg2 = bufA + (long long)MAXN * MAXH2;
        float* p2   = bufB;

        dim3 gg(H2 / 128, cdiv_ll(Nn, 128));
        k_sgemm<<<gg, T>>>(h1, W2,  xw2, Nn, H2, H1);
        k_sgemm<<<gg, T>>>(h1, P2w, p2,  Nn, H2, H1);

        long long tot = (long long)Nn * H2;
        int Hq = H2 >> 2;
        k_csr_agg<<<Nn, Hq>>>((const float4*)xw2, startp, srcs, dinv, b2,
                              (float4*)agg2, Hq);

        k_zero<<<cdiv_ll(H2, T), T>>>(colsum, H2);
        k_zero<<<cdiv_ll(H2, T), T>>>(colsq,  H2);
        k_zero<<<cdiv_ll(H2, T), T>>>(pnsum,  H2);
        k_zero<<<1, 32>>>(scal, 4);

        dim3 gs(cdiv_ll(H2, T), GY);
        k_colstats<<<gs, T>>>(agg2, colsum, colsq, Nn, H2, RPB);
        k_bnfin<<<cdiv_ll(H2, T), T>>>(colsum, colsq, gm2, be2, scale, shift, Nn, H2);
        k_bnrelu_pn<<<gs, T>>>(agg2, scale, shift, xw2, pnsum, scal, Nn, H2, RPB);
        k_pnfin<<<1, 512>>>(pnsum, pnmean, scal, Nn, H2);
        k_combine<<<cdiv_ll(tot, T), T>>>(xw2, pnmean, scal, p2, P2b, out, tot, H2 - 1);
    }
}